// round 2
// baseline (speedup 1.0000x reference)
#include <cuda_runtime.h>
#include <math.h>

// ---------------- problem constants ----------------
#define SEQ   2048
#define EMB   1280
#define RNK   325          // low rank
#define R3    (3*RNK)      // 975
#define NBAT  4
#define TOK   (NBAT*SEQ)   // 8192 tokens

// ---------------- scratch (device globals; no allocations allowed) ----------
__device__ float g_C  [(size_t)SEQ*SEQ];        // cosine "FFT" matrix (16.8 MB)
__device__ float g_xn [(size_t)TOK*EMB];        // layernormed x
__device__ float g_qkv[(size_t)TOK*R3];         // low-rank qkv, [4][2048][975]
__device__ float g_F  [(size_t)TOK*R3];         // C @ qkv   (fft of all 3 ranks)
__device__ float g_M  [(size_t)RNK*RNK];        // Wq @ Wk^T
__device__ float g_T  [(size_t)TOK*RNK];        // Fq @ M
__device__ float g_sc [(size_t)NBAT*SEQ*SEQ];   // scores / attn (67 MB)
__device__ float g_U  [(size_t)TOK*RNK];        // attn @ Fv
__device__ float g_Y  [(size_t)TOK*RNK];        // C @ U  (ifft, rank domain)
__device__ float g_Wvo[(size_t)RNK*EMB];        // Wv @ W_out

// ---------------- C[i][j] = cos(2*pi*i*j/2048) -------------------------------
__global__ void build_cos_kernel()
{
    size_t idx = (size_t)blockIdx.x * 256 + threadIdx.x;   // covers 2048*2048
    int i = (int)(idx >> 11);
    int j = (int)(idx & 2047);
    int m = (i * j) & 2047;                                // exact integer arg reduction
    g_C[idx] = cospif((float)m * (1.0f / 1024.0f));
}

// ---------------- LayerNorm over E=1280 (one block per token) ----------------
__global__ void layernorm_kernel(const float* __restrict__ x,
                                 const float* __restrict__ gamma,
                                 const float* __restrict__ beta,
                                 float* __restrict__ y)
{
    int t   = blockIdx.x;
    int tid = threadIdx.x;
    const float* xr = x + (size_t)t * EMB;
    float*       yr = y + (size_t)t * EMB;

    float lv[5];
    float s = 0.f, s2 = 0.f;
#pragma unroll
    for (int i = 0; i < 5; i++) {               // 1280 = 256*5 exactly
        float v = xr[tid + i * 256];
        lv[i] = v; s += v; s2 += v * v;
    }
#pragma unroll
    for (int o = 16; o > 0; o >>= 1) {
        s  += __shfl_xor_sync(0xffffffffu, s,  o);
        s2 += __shfl_xor_sync(0xffffffffu, s2, o);
    }
    __shared__ float sa[8], sb[8], smu, srs;
    int w = tid >> 5, l = tid & 31;
    if (l == 0) { sa[w] = s; sb[w] = s2; }
    __syncthreads();
    if (tid == 0) {
        float S = 0.f, S2 = 0.f;
#pragma unroll
        for (int i = 0; i < 8; i++) { S += sa[i]; S2 += sb[i]; }
        float mu  = S  * (1.0f / EMB);
        float var = S2 * (1.0f / EMB) - mu * mu;
        smu = mu; srs = rsqrtf(var + 1e-5f);
    }
    __syncthreads();
    float mu = smu, rs = srs;
#pragma unroll
    for (int i = 0; i < 5; i++) {
        int c = tid + i * 256;
        yr[c] = (lv[i] - mu) * rs * gamma[c] + beta[c];
    }
}

// ---------------- softmax(|row|) in place, row length 2048 -------------------
__global__ void softmax_abs_kernel(float* __restrict__ S)
{
    size_t r   = blockIdx.x;
    float* row = S + r * (size_t)SEQ;
    int tid = threadIdx.x;

    float v[8];
    float mx = -1e30f;
#pragma unroll
    for (int i = 0; i < 8; i++) {               // 2048 = 256*8
        v[i] = fabsf(row[tid + i * 256]);
        mx = fmaxf(mx, v[i]);
    }
#pragma unroll
    for (int o = 16; o > 0; o >>= 1) mx = fmaxf(mx, __shfl_xor_sync(0xffffffffu, mx, o));
    __shared__ float sm[8], smax, ssum;
    int w = tid >> 5, l = tid & 31;
    if (l == 0) sm[w] = mx;
    __syncthreads();
    if (tid == 0) {
        float m = sm[0];
#pragma unroll
        for (int i = 1; i < 8; i++) m = fmaxf(m, sm[i]);
        smax = m;
    }
    __syncthreads();
    mx = smax;
    float s = 0.f;
#pragma unroll
    for (int i = 0; i < 8; i++) { v[i] = __expf(v[i] - mx); s += v[i]; }
#pragma unroll
    for (int o = 16; o > 0; o >>= 1) s += __shfl_xor_sync(0xffffffffu, s, o);
    if (l == 0) sm[w] = s;
    __syncthreads();
    if (tid == 0) {
        float t = 0.f;
#pragma unroll
        for (int i = 0; i < 8; i++) t += sm[i];
        ssum = t;
    }
    __syncthreads();
    float inv = 1.0f / ssum;
#pragma unroll
    for (int i = 0; i < 8; i++) row[tid + i * 256] = v[i] * inv;
}

// ---------------- generic fp32 GEMM, 128x128x16 tiles, double-buffered ------
// D[z] = alpha * A[z](MxK) * op(B[z])(KxN)  (+ R[z] if RESID)
// A row-major (lda); B row-major: NN -> B[k*ldb+n], NT -> B[n*ldb+k].
template <bool TRANSB, bool RESID>
__global__ void __launch_bounds__(256)
sgemm_kernel(int M, int N, int K,
             const float* __restrict__ A, int lda, long sA,
             const float* __restrict__ B, int ldb, long sB,
             float* __restrict__ D, int ldd, long sD,
             float alpha, const float* __restrict__ R)
{
    constexpr int BM = 128, BN = 128, BK = 16;
    __shared__ float As[2][BK][BM + 4];
    __shared__ float Bs[2][BK][BN + 4];

    int z = blockIdx.z;
    A += (long)z * sA;
    B += (long)z * sB;
    D += (long)z * sD;
    if (RESID) R += (long)z * sD;

    int bm = blockIdx.y * BM, bn = blockIdx.x * BN;
    int tid = threadIdx.x;
    int tx = tid & 15, ty = tid >> 4;

    // loader coordinates
    int a_k   = tid & 15,  a_m   = tid >> 4;   // m = a_m + i*16
    int bnn_n = tid & 127, bnn_k = tid >> 7;   // NN: k = bnn_k + i*2
    int bnt_k = tid & 15,  bnt_n = tid >> 4;   // NT: n = bnt_n + i*16

    float acc[8][8];
#pragma unroll
    for (int i = 0; i < 8; i++)
#pragma unroll
        for (int j = 0; j < 8; j++) acc[i][j] = 0.f;

    float ra[8], rb[8];
    int ntiles = (K + BK - 1) / BK;

    // prologue: tile 0 straight to smem
    {
#pragma unroll
        for (int i = 0; i < 8; i++) {
            int m = a_m + i * 16;
            int gm = bm + m, gk = a_k;
            As[0][a_k][m] = (gm < M && gk < K) ? A[(long)gm * lda + gk] : 0.f;
        }
        if (!TRANSB) {
#pragma unroll
            for (int i = 0; i < 8; i++) {
                int kk = bnn_k + i * 2;
                int gk = kk, gn = bn + bnn_n;
                Bs[0][kk][bnn_n] = (gk < K && gn < N) ? B[(long)gk * ldb + gn] : 0.f;
            }
        } else {
#pragma unroll
            for (int i = 0; i < 8; i++) {
                int n = bnt_n + i * 16;
                int gn = bn + n, gk = bnt_k;
                Bs[0][bnt_k][n] = (gn < N && gk < K) ? B[(long)gn * ldb + gk] : 0.f;
            }
        }
    }
    __syncthreads();

    for (int t = 0; t < ntiles; t++) {
        int cur = t & 1;
        bool more = (t + 1 < ntiles);
        if (more) {
            int kt = (t + 1) * BK;
#pragma unroll
            for (int i = 0; i < 8; i++) {
                int m = a_m + i * 16;
                int gm = bm + m, gk = kt + a_k;
                ra[i] = (gm < M && gk < K) ? A[(long)gm * lda + gk] : 0.f;
            }
            if (!TRANSB) {
#pragma unroll
                for (int i = 0; i < 8; i++) {
                    int gk = kt + bnn_k + i * 2, gn = bn + bnn_n;
                    rb[i] = (gk < K && gn < N) ? B[(long)gk * ldb + gn] : 0.f;
                }
            } else {
#pragma unroll
                for (int i = 0; i < 8; i++) {
                    int gn = bn + bnt_n + i * 16, gk = kt + bnt_k;
                    rb[i] = (gn < N && gk < K) ? B[(long)gn * ldb + gk] : 0.f;
                }
            }
        }

        // compute on current buffer
#pragma unroll
        for (int kk = 0; kk < BK; kk++) {
            float4 a0 = *reinterpret_cast<const float4*>(&As[cur][kk][ty * 8]);
            float4 a1 = *reinterpret_cast<const float4*>(&As[cur][kk][ty * 8 + 4]);
            float4 b0 = *reinterpret_cast<const float4*>(&Bs[cur][kk][tx * 8]);
            float4 b1 = *reinterpret_cast<const float4*>(&Bs[cur][kk][tx * 8 + 4]);
            float av[8] = {a0.x, a0.y, a0.z, a0.w, a1.x, a1.y, a1.z, a1.w};
            float bv[8] = {b0.x, b0.y, b0.z, b0.w, b1.x, b1.y, b1.z, b1.w};
#pragma unroll
            for (int i = 0; i < 8; i++)
#pragma unroll
                for (int j = 0; j < 8; j++) acc[i][j] += av[i] * bv[j];
        }

        if (more) {
            int nxt = cur ^ 1;
#pragma unroll
            for (int i = 0; i < 8; i++) As[nxt][a_k][a_m + i * 16] = ra[i];
            if (!TRANSB) {
#pragma unroll
                for (int i = 0; i < 8; i++) Bs[nxt][bnn_k + i * 2][bnn_n] = rb[i];
            } else {
#pragma unroll
                for (int i = 0; i < 8; i++) Bs[nxt][bnt_k][bnt_n + i * 16] = rb[i];
            }
            __syncthreads();
        }
    }

    // epilogue
#pragma unroll
    for (int i = 0; i < 8; i++) {
        int gm = bm + ty * 8 + i;
        if (gm >= M) continue;
#pragma unroll
        for (int j = 0; j < 8; j++) {
            int gn = bn + tx * 8 + j;
            if (gn >= N) continue;
            float vv = alpha * acc[i][j];
            if (RESID) vv += R[(long)gm * ldd + gn];
            D[(long)gm * ldd + gn] = vv;
        }
    }
}

static inline dim3 gemm_grid(int M, int N, int Z) {
    return dim3((N + 127) / 128, (M + 127) / 128, Z);
}

// ---------------- host orchestration ----------------------------------------
// Math (exact reassociation of the reference):
//   F  = C @ qkv                      (fft of all three rank tensors at once)
//   scores = (Fq (Wq Wk^T) Fk^T) / sqrt(160)
//   attn   = softmax(|scores|)
//   out    = x + (C @ (attn @ Fv)) @ (Wv W_out) / 2048
extern "C" void kernel_launch(void* const* d_in, const int* in_sizes, int n_in,
                              void* d_out, int out_size)
{
    const float* x     = (const float*)d_in[0];   // (4,2048,1280)
    const float* Wqkv  = (const float*)d_in[1];   // (1280, 975)
    const float* Wq    = (const float*)d_in[2];   // (325, 1280)
    const float* Wk    = (const float*)d_in[3];   // (325, 1280)
    const float* Wv    = (const float*)d_in[4];   // (325, 1280)
    const float* Wout  = (const float*)d_in[5];   // (1280, 1280)
    const float* gamma = (const float*)d_in[6];
    const float* beta  = (const float*)d_in[7];
    float* out = (float*)d_out;

    float *C, *xn, *qkv, *F, *M, *T, *sc, *U, *Y, *Wvo;
    cudaGetSymbolAddress((void**)&C,   g_C);
    cudaGetSymbolAddress((void**)&xn,  g_xn);
    cudaGetSymbolAddress((void**)&qkv, g_qkv);
    cudaGetSymbolAddress((void**)&F,   g_F);
    cudaGetSymbolAddress((void**)&M,   g_M);
    cudaGetSymbolAddress((void**)&T,   g_T);
    cudaGetSymbolAddress((void**)&sc,  g_sc);
    cudaGetSymbolAddress((void**)&U,   g_U);
    cudaGetSymbolAddress((void**)&Y,   g_Y);
    cudaGetSymbolAddress((void**)&Wvo, g_Wvo);

    const long sF = (long)SEQ * R3;        // per-batch stride of qkv / F
    const long sR = (long)SEQ * RNK;       // per-batch stride of T / U / Y
    const long sS = (long)SEQ * SEQ;       // per-batch stride of scores
    const float inv_sqrt_hd = 0.07905694150420949f;  // 1/sqrt(160)

    // 0. cosine matrix (rebuilt every call: no caching allowed)
    build_cos_kernel<<<(SEQ * SEQ) / 256, 256>>>();

    // 1. LayerNorm
    layernorm_kernel<<<TOK, 256>>>(x, gamma, beta, xn);

    // 2. qkv = xn @ W_qkv                 (8192 x 975 x 1280)
    sgemm_kernel<false, false><<<gemm_grid(TOK, R3, 1), 256>>>(
        TOK, R3, EMB, xn, EMB, 0L, Wqkv, R3, 0L, qkv, R3, 0L, 1.f, nullptr);

    // 3. F = C @ qkv  (fft of q,k,v ranks together; z=4: 2048 x 975 x 2048)
    sgemm_kernel<false, false><<<gemm_grid(SEQ, R3, NBAT), 256>>>(
        SEQ, R3, SEQ, C, SEQ, 0L, qkv, R3, sF, F, R3, sF, 1.f, nullptr);

    // 4. M = Wq @ Wk^T                    (325 x 325 x 1280, NT)
    sgemm_kernel<true, false><<<gemm_grid(RNK, RNK, 1), 256>>>(
        RNK, RNK, EMB, Wq, EMB, 0L, Wk, EMB, 0L, M, RNK, 0L, 1.f, nullptr);

    // 5. T = Fq @ M                       (z=4: 2048 x 325 x 325)
    sgemm_kernel<false, false><<<gemm_grid(SEQ, RNK, NBAT), 256>>>(
        SEQ, RNK, RNK, F + 0 * RNK, R3, sF, M, RNK, 0L, T, RNK, sR, 1.f, nullptr);

    // 6. scores = (T @ Fk^T) / sqrt(160)  (z=4: 2048 x 2048 x 325, NT)
    sgemm_kernel<true, false><<<gemm_grid(SEQ, SEQ, NBAT), 256>>>(
        SEQ, SEQ, RNK, T, RNK, sR, F + 1 * RNK, R3, sF, sc, SEQ, sS, inv_sqrt_hd, nullptr);

    // 7. attn = softmax(|scores|) rowwise, in place
    softmax_abs_kernel<<<NBAT * SEQ, 256>>>(sc);

    // 8. U = attn @ Fv                    (z=4: 2048 x 325 x 2048)
    sgemm_kernel<false, false><<<gemm_grid(SEQ, RNK, NBAT), 256>>>(
        SEQ, RNK, SEQ, sc, SEQ, sS, F + 2 * RNK, R3, sF, U, RNK, sR, 1.f, nullptr);

    // 9. Y = C @ U  (ifft in rank domain; z=4: 2048 x 325 x 2048)
    sgemm_kernel<false, false><<<gemm_grid(SEQ, RNK, NBAT), 256>>>(
        SEQ, RNK, SEQ, C, SEQ, 0L, U, RNK, sR, Y, RNK, sR, 1.f, nullptr);

    // 10. Wvo = Wv @ W_out                (325 x 1280 x 1280)
    sgemm_kernel<false, false><<<gemm_grid(RNK, EMB, 1), 256>>>(
        RNK, EMB, EMB, Wv, EMB, 0L, Wout, EMB, 0L, Wvo, EMB, 0L, 1.f, nullptr);

    // 11. out = x + (Y @ Wvo) / 2048      (8192 x 1280 x 325, residual)
    sgemm_kernel<false, true><<<gemm_grid(TOK, EMB, 1), 256>>>(
        TOK, EMB, RNK, Y, RNK, 0L, Wvo, EMB, 0L, out, EMB, 0L, 1.0f / 2048.0f, x);
}

// round 5
// speedup vs baseline: 1.2220x; 1.2220x over previous
#include <cuda_runtime.h>
#include <math.h>

// ---------------- problem constants ----------------
#define SEQ   2048
#define EMB   1280
#define RNK   325          // low rank
#define R3    (3*RNK)      // 975
#define NBAT  4
#define TOK   (NBAT*SEQ)   // 8192 tokens

// ---------------- scratch (device globals; no allocations allowed) ----------
__device__ float g_C  [(size_t)SEQ*SEQ];        // cosine "FFT" matrix (16.8 MB)
__device__ float g_xn [(size_t)TOK*EMB];        // layernormed x
__device__ float g_qkv[(size_t)TOK*R3];         // low-rank qkv, [4][2048][975]
__device__ float g_F  [(size_t)TOK*R3];         // C @ qkv
__device__ float g_M  [(size_t)RNK*RNK];        // Wq @ Wk^T
__device__ float g_T  [(size_t)TOK*RNK];        // Fq @ M
__device__ float g_sc [(size_t)NBAT*SEQ*SEQ];   // scores / attn (67 MB)
__device__ float g_U  [(size_t)TOK*RNK];        // attn @ Fv
__device__ float g_Y  [(size_t)TOK*RNK];        // C @ U
__device__ float g_Wvo[(size_t)RNK*EMB];        // Wv @ W_out

// ---------------- helpers ----------------------------------------------------
__device__ __forceinline__ unsigned f2tf32(float x) {
    unsigned r;
    asm("cvt.rna.tf32.f32 %0, %1;" : "=r"(r) : "f"(x));
    return r;
}
__device__ __forceinline__ float tf32f(float x) {           // round-to-tf32, as float
    return __uint_as_float(f2tf32(x));
}
__device__ __forceinline__ void mma_tf32(float (&c)[4],
                                         const unsigned (&a)[4],
                                         const unsigned (&b)[2]) {
    asm volatile(
        "mma.sync.aligned.m16n8k8.row.col.f32.tf32.tf32.f32 "
        "{%0,%1,%2,%3}, {%4,%5,%6,%7}, {%8,%9}, {%0,%1,%2,%3};"
        : "+f"(c[0]), "+f"(c[1]), "+f"(c[2]), "+f"(c[3])
        : "r"(a[0]), "r"(a[1]), "r"(a[2]), "r"(a[3]), "r"(b[0]), "r"(b[1]));
}

// ---------------- C[i][j] = cos(2*pi*i*j/2048) -------------------------------
__global__ void build_cos_kernel()
{
    size_t idx = (size_t)blockIdx.x * 256 + threadIdx.x;
    int i = (int)(idx >> 11);
    int j = (int)(idx & 2047);
    int m = (i * j) & 2047;                                // exact integer reduction
    g_C[idx] = cospif((float)m * (1.0f / 1024.0f));
}

// ---------------- LayerNorm over E=1280 (one block per token) ----------------
__global__ void layernorm_kernel(const float* __restrict__ x,
                                 const float* __restrict__ gamma,
                                 const float* __restrict__ beta,
                                 float* __restrict__ y)
{
    int t   = blockIdx.x;
    int tid = threadIdx.x;
    const float* xr = x + (size_t)t * EMB;
    float*       yr = y + (size_t)t * EMB;

    float lv[5];
    float s = 0.f, s2 = 0.f;
#pragma unroll
    for (int i = 0; i < 5; i++) {
        float v = xr[tid + i * 256];
        lv[i] = v; s += v; s2 += v * v;
    }
#pragma unroll
    for (int o = 16; o > 0; o >>= 1) {
        s  += __shfl_xor_sync(0xffffffffu, s,  o);
        s2 += __shfl_xor_sync(0xffffffffu, s2, o);
    }
    __shared__ float sa[8], sb[8], smu, srs;
    int w = tid >> 5, l = tid & 31;
    if (l == 0) { sa[w] = s; sb[w] = s2; }
    __syncthreads();
    if (tid == 0) {
        float S = 0.f, S2 = 0.f;
#pragma unroll
        for (int i = 0; i < 8; i++) { S += sa[i]; S2 += sb[i]; }
        float mu  = S  * (1.0f / EMB);
        float var = S2 * (1.0f / EMB) - mu * mu;
        smu = mu; srs = rsqrtf(var + 1e-5f);
    }
    __syncthreads();
    float mu = smu, rs = srs;
#pragma unroll
    for (int i = 0; i < 5; i++) {
        int c = tid + i * 256;
        yr[c] = (lv[i] - mu) * rs * gamma[c] + beta[c];
    }
}

// ---------------- softmax(|row|) in place, row length 2048 -------------------
__global__ void softmax_abs_kernel(float* __restrict__ S)
{
    size_t r   = blockIdx.x;
    float* row = S + r * (size_t)SEQ;
    int tid = threadIdx.x;

    float v[8];
    float mx = -1e30f;
#pragma unroll
    for (int i = 0; i < 8; i++) {
        v[i] = fabsf(row[tid + i * 256]);
        mx = fmaxf(mx, v[i]);
    }
#pragma unroll
    for (int o = 16; o > 0; o >>= 1) mx = fmaxf(mx, __shfl_xor_sync(0xffffffffu, mx, o));
    __shared__ float sm[8], smax, ssum;
    int w = tid >> 5, l = tid & 31;
    if (l == 0) sm[w] = mx;
    __syncthreads();
    if (tid == 0) {
        float m = sm[0];
#pragma unroll
        for (int i = 1; i < 8; i++) m = fmaxf(m, sm[i]);
        smax = m;
    }
    __syncthreads();
    mx = smax;
    float s = 0.f;
#pragma unroll
    for (int i = 0; i < 8; i++) { v[i] = __expf(v[i] - mx); s += v[i]; }
#pragma unroll
    for (int o = 16; o > 0; o >>= 1) s += __shfl_xor_sync(0xffffffffu, s, o);
    if (l == 0) sm[w] = s;
    __syncthreads();
    if (tid == 0) {
        float t = 0.f;
#pragma unroll
        for (int i = 0; i < 8; i++) t += sm[i];
        ssum = t;
    }
    __syncthreads();
    float inv = 1.0f / ssum;
#pragma unroll
    for (int i = 0; i < 8; i++) row[tid + i * 256] = v[i] * inv;
}

// ---------------- tf32 tensor-core GEMM --------------------------------------
// D[z] = alpha * A[z](MxK) * op(B[z])(KxN)  (+ R[z] if RESID)
// A row-major (lda); B row-major: NN -> B[k*ldb+n], NT -> B[n*ldb+k].
// COMP: tf32x3 error-compensated (hi/lo split of both operands), near-fp32.
// Block: 256 threads = 8 warps (2x4), tile 128x128, BK=16, warp tile 64x32.
template <bool TRANSB, bool RESID, bool COMP>
__global__ void __launch_bounds__(256, 1)
tgemm_kernel(int M, int N, int K,
             const float* __restrict__ A, int lda, long sA,
             const float* __restrict__ B, int ldb, long sB,
             float* __restrict__ D, int ldd, long sD,
             float alpha, const float* __restrict__ R)
{
    constexpr int BM = 128, BN = 128, BK = 16;
    constexpr int LDS_A = BM + 4, LDS_B = BN + 4;   // stride%32 == 4 -> frag loads conflict-free
    constexpr int NSP = COMP ? 2 : 1;               // hi (+ lo) planes
    __shared__ float As[NSP][BK][LDS_A];
    __shared__ float Bs[NSP][BK][LDS_B];

    int z = blockIdx.z;
    A += (long)z * sA;
    B += (long)z * sB;
    D += (long)z * sD;
    if (RESID) R += (long)z * sD;

    const int bm = blockIdx.y * BM, bn = blockIdx.x * BN;
    const int tid = threadIdx.x;

    // loader coordinates
    const int a_k   = tid & 15,  a_m   = tid >> 4;   // A: m = a_m + i*16
    const int bnn_n = tid & 127, bnn_k = tid >> 7;   // NN: k = bnn_k + i*2
    const int bnt_k = tid & 15,  bnt_n = tid >> 4;   // NT: n = bnt_n + i*16

    // mma coordinates
    const int warp = tid >> 5, lane = tid & 31;
    const int wm = warp & 1, wn = warp >> 1;         // 2 x 4 warp grid
    const int am_base = wm * 64;                     // + i*16, i<4
    const int bn_base = wn * 32;                     // + j*8,  j<4
    const int qr = lane >> 2, qc = lane & 3;

    float acc[4][4][4];
#pragma unroll
    for (int i = 0; i < 4; i++)
#pragma unroll
        for (int j = 0; j < 4; j++)
#pragma unroll
            for (int e = 0; e < 4; e++) acc[i][j][e] = 0.f;

    float ra[8], rb[8];
    const int ntiles = (K + BK - 1) / BK;

    auto load_regs = [&](int kt) {
#pragma unroll
        for (int i = 0; i < 8; i++) {
            int gm = bm + a_m + i * 16, gk = kt + a_k;
            ra[i] = (gm < M && gk < K) ? A[(long)gm * lda + gk] : 0.f;
        }
        if (!TRANSB) {
#pragma unroll
            for (int i = 0; i < 8; i++) {
                int gk = kt + bnn_k + i * 2, gn = bn + bnn_n;
                rb[i] = (gk < K && gn < N) ? B[(long)gk * ldb + gn] : 0.f;
            }
        } else {
#pragma unroll
            for (int i = 0; i < 8; i++) {
                int gn = bn + bnt_n + i * 16, gk = kt + bnt_k;
                rb[i] = (gn < N && gk < K) ? B[(long)gn * ldb + gk] : 0.f;
            }
        }
    };

    auto store_smem = [&]() {
#pragma unroll
        for (int i = 0; i < 8; i++) {
            float hi = tf32f(ra[i]);
            As[0][a_k][a_m + i * 16] = hi;
            if (COMP) As[1][a_k][a_m + i * 16] = tf32f(ra[i] - hi);
        }
        if (!TRANSB) {
#pragma unroll
            for (int i = 0; i < 8; i++) {
                float hi = tf32f(rb[i]);
                Bs[0][bnn_k + i * 2][bnn_n] = hi;
                if (COMP) Bs[1][bnn_k + i * 2][bnn_n] = tf32f(rb[i] - hi);
            }
        } else {
#pragma unroll
            for (int i = 0; i < 8; i++) {
                float hi = tf32f(rb[i]);
                Bs[0][bnt_k][bnt_n + i * 16] = hi;
                if (COMP) Bs[1][bnt_k][bnt_n + i * 16] = tf32f(rb[i] - hi);
            }
        }
    };

    // prologue
    load_regs(0);
    store_smem();
    __syncthreads();

    for (int t = 0; t < ntiles; t++) {
        bool more = (t + 1 < ntiles);
        if (more) load_regs((t + 1) * BK);

        // compute on current smem tile
#pragma unroll
        for (int ks = 0; ks < 2; ks++) {
            const int k0 = ks * 8;
            unsigned bh[4][2], bl[4][2];
#pragma unroll
            for (int j = 0; j < 4; j++) {
                int n = bn_base + j * 8 + qr;
                bh[j][0] = __float_as_uint(Bs[0][k0 + qc][n]);
                bh[j][1] = __float_as_uint(Bs[0][k0 + 4 + qc][n]);
                if (COMP) {
                    bl[j][0] = __float_as_uint(Bs[1][k0 + qc][n]);
                    bl[j][1] = __float_as_uint(Bs[1][k0 + 4 + qc][n]);
                }
            }
#pragma unroll
            for (int i = 0; i < 4; i++) {
                int m = am_base + i * 16 + qr;
                unsigned ah[4], al[4];
                ah[0] = __float_as_uint(As[0][k0 + qc][m]);
                ah[1] = __float_as_uint(As[0][k0 + qc][m + 8]);
                ah[2] = __float_as_uint(As[0][k0 + 4 + qc][m]);
                ah[3] = __float_as_uint(As[0][k0 + 4 + qc][m + 8]);
                if (COMP) {
                    al[0] = __float_as_uint(As[1][k0 + qc][m]);
                    al[1] = __float_as_uint(As[1][k0 + qc][m + 8]);
                    al[2] = __float_as_uint(As[1][k0 + 4 + qc][m]);
                    al[3] = __float_as_uint(As[1][k0 + 4 + qc][m + 8]);
                }
#pragma unroll
                for (int j = 0; j < 4; j++) {
                    if (COMP) {
                        mma_tf32(acc[i][j], al, bh[j]);   // A_lo * B_hi
                        mma_tf32(acc[i][j], ah, bl[j]);   // A_hi * B_lo
                    }
                    mma_tf32(acc[i][j], ah, bh[j]);       // A_hi * B_hi (last: largest term)
                }
            }
        }

        __syncthreads();
        if (more) {
            store_smem();
            __syncthreads();
        }
    }

    // epilogue: c0,c1 at (r, c),(r, c+1); c2,c3 at (r+8, ...)
#pragma unroll
    for (int i = 0; i < 4; i++) {
#pragma unroll
        for (int j = 0; j < 4; j++) {
            int r0 = bm + am_base + i * 16 + qr;
            int c0 = bn + bn_base + j * 8 + qc * 2;
#pragma unroll
            for (int half = 0; half < 2; half++) {
                int r = r0 + half * 8;
                if (r >= M) continue;
                float v0 = alpha * acc[i][j][half * 2 + 0];
                float v1 = alpha * acc[i][j][half * 2 + 1];
                if (c0 < N) {
                    if (RESID) v0 += R[(long)r * ldd + c0];
                    D[(long)r * ldd + c0] = v0;
                }
                if (c0 + 1 < N) {
                    if (RESID) v1 += R[(long)r * ldd + c0 + 1];
                    D[(long)r * ldd + c0 + 1] = v1;
                }
            }
        }
    }
}

static inline dim3 gemm_grid(int M, int N, int Z) {
    return dim3((N + 127) / 128, (M + 127) / 128, Z);
}

// ---------------- host orchestration ----------------------------------------
// Math (exact reassociation of the reference):
//   F  = C @ qkv
//   scores = (Fq (Wq Wk^T) Fk^T) / sqrt(160)
//   attn   = softmax(|scores|)
//   out    = x + (C @ (attn @ Fv)) @ (Wv W_out) / 2048
// Pre-softmax GEMMs use tf32x3 compensation (near-fp32 logits);
// post-softmax GEMMs use plain tf32.
extern "C" void kernel_launch(void* const* d_in, const int* in_sizes, int n_in,
                              void* d_out, int out_size)
{
    const float* x     = (const float*)d_in[0];   // (4,2048,1280)
    const float* Wqkv  = (const float*)d_in[1];   // (1280, 975)
    const float* Wq    = (const float*)d_in[2];   // (325, 1280)
    const float* Wk    = (const float*)d_in[3];   // (325, 1280)
    const float* Wv    = (const float*)d_in[4];   // (325, 1280)
    const float* Wout  = (const float*)d_in[5];   // (1280, 1280)
    const float* gamma = (const float*)d_in[6];
    const float* beta  = (const float*)d_in[7];
    float* out = (float*)d_out;

    float *C, *xn, *qkv, *F, *M, *T, *sc, *U, *Y, *Wvo;
    cudaGetSymbolAddress((void**)&C,   g_C);
    cudaGetSymbolAddress((void**)&xn,  g_xn);
    cudaGetSymbolAddress((void**)&qkv, g_qkv);
    cudaGetSymbolAddress((void**)&F,   g_F);
    cudaGetSymbolAddress((void**)&M,   g_M);
    cudaGetSymbolAddress((void**)&T,   g_T);
    cudaGetSymbolAddress((void**)&sc,  g_sc);
    cudaGetSymbolAddress((void**)&U,   g_U);
    cudaGetSymbolAddress((void**)&Y,   g_Y);
    cudaGetSymbolAddress((void**)&Wvo, g_Wvo);

    const long sF = (long)SEQ * R3;        // per-batch stride of qkv / F
    const long sR = (long)SEQ * RNK;       // per-batch stride of T / U / Y
    const long sS = (long)SEQ * SEQ;       // per-batch stride of scores
    const float inv_sqrt_hd = 0.07905694150420949f;  // 1/sqrt(160)

    // 0. cosine matrix (rebuilt every call: no caching allowed)
    build_cos_kernel<<<(SEQ * SEQ) / 256, 256>>>();

    // 1. LayerNorm
    layernorm_kernel<<<TOK, 256>>>(x, gamma, beta, xn);

    // 2. qkv = xn @ W_qkv                 (8192 x 975 x 1280)  [COMP]
    tgemm_kernel<false, false, true><<<gemm_grid(TOK, R3, 1), 256>>>(
        TOK, R3, EMB, xn, EMB, 0L, Wqkv, R3, 0L, qkv, R3, 0L, 1.f, nullptr);

    // 3. F = C @ qkv                      (z=4: 2048 x 975 x 2048)  [COMP]
    tgemm_kernel<false, false, true><<<gemm_grid(SEQ, R3, NBAT), 256>>>(
        SEQ, R3, SEQ, C, SEQ, 0L, qkv, R3, sF, F, R3, sF, 1.f, nullptr);

    // 4. M = Wq @ Wk^T                    (325 x 325 x 1280, NT)  [COMP]
    tgemm_kernel<true, false, true><<<gemm_grid(RNK, RNK, 1), 256>>>(
        RNK, RNK, EMB, Wq, EMB, 0L, Wk, EMB, 0L, M, RNK, 0L, 1.f, nullptr);

    // 5. T = Fq @ M                       (z=4: 2048 x 325 x 325)  [COMP]
    tgemm_kernel<false, false, true><<<gemm_grid(SEQ, RNK, NBAT), 256>>>(
        SEQ, RNK, RNK, F + 0 * RNK, R3, sF, M, RNK, 0L, T, RNK, sR, 1.f, nullptr);

    // 6. scores = (T @ Fk^T) / sqrt(160)  (z=4: 2048 x 2048 x 325, NT)  [COMP]
    tgemm_kernel<true, false, true><<<gemm_grid(SEQ, SEQ, NBAT), 256>>>(
        SEQ, SEQ, RNK, T, RNK, sR, F + 1 * RNK, R3, sF, sc, SEQ, sS, inv_sqrt_hd, nullptr);

    // 7. attn = softmax(|scores|) rowwise, in place
    softmax_abs_kernel<<<NBAT * SEQ, 256>>>(sc);

    // 8. U = attn @ Fv                    (z=4: 2048 x 325 x 2048)  [tf32]
    tgemm_kernel<false, false, false><<<gemm_grid(SEQ, RNK, NBAT), 256>>>(
        SEQ, RNK, SEQ, sc, SEQ, sS, F + 2 * RNK, R3, sF, U, RNK, sR, 1.f, nullptr);

    // 9. Y = C @ U                        (z=4: 2048 x 325 x 2048)  [tf32]
    tgemm_kernel<false, false, false><<<gemm_grid(SEQ, RNK, NBAT), 256>>>(
        SEQ, RNK, SEQ, C, SEQ, 0L, U, RNK, sR, Y, RNK, sR, 1.f, nullptr);

    // 10. Wvo = Wv @ W_out                (325 x 1280 x 1280)  [tf32]
    tgemm_kernel<false, false, false><<<gemm_grid(RNK, EMB, 1), 256>>>(
        RNK, EMB, EMB, Wv, EMB, 0L, Wout, EMB, 0L, Wvo, EMB, 0L, 1.f, nullptr);

    // 11. out = x + (Y @ Wvo) / 2048      (8192 x 1280 x 325, residual)  [tf32]
    tgemm_kernel<false, true, false><<<gemm_grid(TOK, EMB, 1), 256>>>(
        TOK, EMB, RNK, Y, RNK, 0L, Wvo, EMB, 0L, out, EMB, 0L, 1.0f / 2048.0f, x);
}

// round 6
// speedup vs baseline: 1.9173x; 1.5691x over previous
#include <cuda_runtime.h>
#include <math.h>

// ---------------- problem constants ----------------
#define SEQ   2048
#define EMB   1280
#define RNK   325          // low rank
#define R3    (3*RNK)      // 975
#define NBAT  4
#define TOK   (NBAT*SEQ)   // 8192 tokens

// ---------------- scratch (device globals; no allocations allowed) ----------
__device__ float g_xn [(size_t)TOK*EMB];        // layernormed x
__device__ float g_qkv[(size_t)TOK*R3];         // low-rank qkv, [4][2048][975]
__device__ float g_F  [(size_t)TOK*R3];         // Re(FFT(qkv)) along seq
__device__ float g_M  [(size_t)RNK*RNK];        // Wq @ Wk^T
__device__ float g_T  [(size_t)TOK*RNK];        // Fq @ M
__device__ float g_sc [(size_t)NBAT*SEQ*SEQ];   // scores / attn (67 MB)
__device__ float g_U  [(size_t)TOK*RNK];        // attn @ Fv
__device__ float g_Y  [(size_t)TOK*RNK];        // Re(FFT(U))  (== C @ U)
__device__ float g_Wvo[(size_t)RNK*EMB];        // Wv @ W_out

// ---------------- helpers ----------------------------------------------------
__device__ __forceinline__ unsigned f2tf32(float x) {
    unsigned r;
    asm("cvt.rna.tf32.f32 %0, %1;" : "=r"(r) : "f"(x));
    return r;
}
__device__ __forceinline__ float tf32f(float x) {           // round-to-tf32, as float
    return __uint_as_float(f2tf32(x));
}
__device__ __forceinline__ void mma_tf32(float (&c)[4],
                                         const unsigned (&a)[4],
                                         const unsigned (&b)[2]) {
    asm volatile(
        "mma.sync.aligned.m16n8k8.row.col.f32.tf32.tf32.f32 "
        "{%0,%1,%2,%3}, {%4,%5,%6,%7}, {%8,%9}, {%0,%1,%2,%3};"
        : "+f"(c[0]), "+f"(c[1]), "+f"(c[2]), "+f"(c[3])
        : "r"(a[0]), "r"(a[1]), "r"(a[2]), "r"(a[3]), "r"(b[0]), "r"(b[1]));
}

// ---------------- batched 2048-pt FFT along seq, keep real part --------------
// One block = one column. in/out: element n of column (z,c) at base + n*stride.
// Computes out[k] = scale * Re( sum_n in[n] * exp(-2*pi*i*k*n/2048) )
//                 = scale * (C @ in)[k]   with C[k][n] = cos(2*pi*k*n/2048)
// In-place radix-2 DIT on bit-reversed input, fp32 (more precise than tf32x3).
__global__ void __launch_bounds__(256)
fft_real_kernel(const float* __restrict__ in, float* __restrict__ out,
                int stride, long zstride, float scale)
{
    __shared__ float re[SEQ];
    __shared__ float im[SEQ];

    const int c = blockIdx.x;
    const int z = blockIdx.y;
    const float* src = in  + (long)z * zstride + c;
    float*       dst = out + (long)z * zstride + c;
    const int tid = threadIdx.x;

    // load with bit-reversal (11-bit), imag = 0
#pragma unroll
    for (int i = 0; i < 8; i++) {
        int n = tid + i * 256;
        int r = __brev((unsigned)n) >> 21;
        re[r] = src[(long)n * stride];
        im[r] = 0.f;
    }
    __syncthreads();

    // 11 radix-2 stages, 1024 butterflies each (4 per thread)
#pragma unroll
    for (int s = 1; s <= 11; s++) {
        const int half = 1 << (s - 1);
#pragma unroll
        for (int i = 0; i < 4; i++) {
            int b   = tid + i * 256;             // butterfly id 0..1023
            int j   = b & (half - 1);
            int grp = b >> (s - 1);
            int i0  = (grp << s) + j;
            int i1  = i0 + half;
            float sn, cs;
            sincospif(-(float)j / (float)half, &sn, &cs);   // w = cs + i*sn
            float xr = re[i1], xi = im[i1];
            float tr = xr * cs - xi * sn;
            float ti = xr * sn + xi * cs;
            float ur = re[i0], ui = im[i0];
            re[i0] = ur + tr;  im[i0] = ui + ti;
            re[i1] = ur - tr;  im[i1] = ui - ti;
        }
        __syncthreads();
    }

    // store real part (natural order)
#pragma unroll
    for (int i = 0; i < 8; i++) {
        int n = tid + i * 256;
        dst[(long)n * stride] = scale * re[n];
    }
}

// ---------------- LayerNorm over E=1280 (one block per token) ----------------
__global__ void layernorm_kernel(const float* __restrict__ x,
                                 const float* __restrict__ gamma,
                                 const float* __restrict__ beta,
                                 float* __restrict__ y)
{
    int t   = blockIdx.x;
    int tid = threadIdx.x;
    const float* xr = x + (size_t)t * EMB;
    float*       yr = y + (size_t)t * EMB;

    float lv[5];
    float s = 0.f, s2 = 0.f;
#pragma unroll
    for (int i = 0; i < 5; i++) {
        float v = xr[tid + i * 256];
        lv[i] = v; s += v; s2 += v * v;
    }
#pragma unroll
    for (int o = 16; o > 0; o >>= 1) {
        s  += __shfl_xor_sync(0xffffffffu, s,  o);
        s2 += __shfl_xor_sync(0xffffffffu, s2, o);
    }
    __shared__ float sa[8], sb[8], smu, srs;
    int w = tid >> 5, l = tid & 31;
    if (l == 0) { sa[w] = s; sb[w] = s2; }
    __syncthreads();
    if (tid == 0) {
        float S = 0.f, S2 = 0.f;
#pragma unroll
        for (int i = 0; i < 8; i++) { S += sa[i]; S2 += sb[i]; }
        float mu  = S  * (1.0f / EMB);
        float var = S2 * (1.0f / EMB) - mu * mu;
        smu = mu; srs = rsqrtf(var + 1e-5f);
    }
    __syncthreads();
    float mu = smu, rs = srs;
#pragma unroll
    for (int i = 0; i < 5; i++) {
        int c = tid + i * 256;
        yr[c] = (lv[i] - mu) * rs * gamma[c] + beta[c];
    }
}

// ---------------- softmax(|row|) in place, row length 2048 -------------------
__global__ void softmax_abs_kernel(float* __restrict__ S)
{
    size_t r   = blockIdx.x;
    float* row = S + r * (size_t)SEQ;
    int tid = threadIdx.x;

    float v[8];
    float mx = -1e30f;
#pragma unroll
    for (int i = 0; i < 8; i++) {
        v[i] = fabsf(row[tid + i * 256]);
        mx = fmaxf(mx, v[i]);
    }
#pragma unroll
    for (int o = 16; o > 0; o >>= 1) mx = fmaxf(mx, __shfl_xor_sync(0xffffffffu, mx, o));
    __shared__ float sm[8], smax, ssum;
    int w = tid >> 5, l = tid & 31;
    if (l == 0) sm[w] = mx;
    __syncthreads();
    if (tid == 0) {
        float m = sm[0];
#pragma unroll
        for (int i = 1; i < 8; i++) m = fmaxf(m, sm[i]);
        smax = m;
    }
    __syncthreads();
    mx = smax;
    float s = 0.f;
#pragma unroll
    for (int i = 0; i < 8; i++) { v[i] = __expf(v[i] - mx); s += v[i]; }
#pragma unroll
    for (int o = 16; o > 0; o >>= 1) s += __shfl_xor_sync(0xffffffffu, s, o);
    if (l == 0) sm[w] = s;
    __syncthreads();
    if (tid == 0) {
        float t = 0.f;
#pragma unroll
        for (int i = 0; i < 8; i++) t += sm[i];
        ssum = t;
    }
    __syncthreads();
    float inv = 1.0f / ssum;
#pragma unroll
    for (int i = 0; i < 8; i++) row[tid + i * 256] = v[i] * inv;
}

// ---------------- tf32 tensor-core GEMM, 2-stage double-buffered -------------
// D[z] = alpha * A[z](MxK) * op(B[z])(KxN)  (+ R[z] if RESID)
// A row-major (lda); B row-major: NN -> B[k*ldb+n], NT -> B[n*ldb+k].
// COMP: tf32x3 error-compensated (hi/lo split of both operands), near-fp32.
// Block: 256 threads = 8 warps (2x4), tile 128x128, BK=16, warp tile 64x32.
// Dynamic smem: 2 stages -> one __syncthreads per K-tile.
template <bool TRANSB, bool RESID, bool COMP>
__global__ void __launch_bounds__(256, 1)
tgemm_kernel(int M, int N, int K,
             const float* __restrict__ A, int lda, long sA,
             const float* __restrict__ B, int ldb, long sB,
             float* __restrict__ D, int ldd, long sD,
             float alpha, const float* __restrict__ R)
{
    constexpr int BM = 128, BN = 128, BK = 16;
    constexpr int LDS_A = BM + 4, LDS_B = BN + 4;
    constexpr int NSP = COMP ? 2 : 1;
    constexpr int APLANE = BK * LDS_A;
    constexpr int BPLANE = BK * LDS_B;
    constexpr int STAGE  = NSP * (APLANE + BPLANE);
    extern __shared__ float smem[];

    int z = blockIdx.z;
    A += (long)z * sA;
    B += (long)z * sB;
    D += (long)z * sD;
    if (RESID) R += (long)z * sD;

    const int bm = blockIdx.y * BM, bn = blockIdx.x * BN;
    const int tid = threadIdx.x;

    // loader coordinates
    const int a_k   = tid & 15,  a_m   = tid >> 4;   // A: m = a_m + i*16
    const int bnn_n = tid & 127, bnn_k = tid >> 7;   // NN: k = bnn_k + i*2
    const int bnt_k = tid & 15,  bnt_n = tid >> 4;   // NT: n = bnt_n + i*16

    // mma coordinates
    const int warp = tid >> 5, lane = tid & 31;
    const int wm = warp & 1, wn = warp >> 1;         // 2 x 4 warp grid
    const int am_base = wm * 64;                     // + i*16, i<4
    const int bn_base = wn * 32;                     // + j*8,  j<4
    const int qr = lane >> 2, qc = lane & 3;

    float acc[4][4][4];
#pragma unroll
    for (int i = 0; i < 4; i++)
#pragma unroll
        for (int j = 0; j < 4; j++)
#pragma unroll
            for (int e = 0; e < 4; e++) acc[i][j][e] = 0.f;

    float ra[8], rb[8];
    const int ntiles = (K + BK - 1) / BK;

    auto load_regs = [&](int kt) {
#pragma unroll
        for (int i = 0; i < 8; i++) {
            int gm = bm + a_m + i * 16, gk = kt + a_k;
            ra[i] = (gm < M && gk < K) ? A[(long)gm * lda + gk] : 0.f;
        }
        if (!TRANSB) {
#pragma unroll
            for (int i = 0; i < 8; i++) {
                int gk = kt + bnn_k + i * 2, gn = bn + bnn_n;
                rb[i] = (gk < K && gn < N) ? B[(long)gk * ldb + gn] : 0.f;
            }
        } else {
#pragma unroll
            for (int i = 0; i < 8; i++) {
                int gn = bn + bnt_n + i * 16, gk = kt + bnt_k;
                rb[i] = (gn < N && gk < K) ? B[(long)gn * ldb + gk] : 0.f;
            }
        }
    };

    auto store_smem = [&](int st) {
        float* A0 = smem + st * STAGE;
        float* A1 = A0 + APLANE;                    // used only when COMP
        float* B0 = A0 + NSP * APLANE;
        float* B1 = B0 + BPLANE;
#pragma unroll
        for (int i = 0; i < 8; i++) {
            float hi = tf32f(ra[i]);
            A0[a_k * LDS_A + a_m + i * 16] = hi;
            if (COMP) A1[a_k * LDS_A + a_m + i * 16] = tf32f(ra[i] - hi);
        }
        if (!TRANSB) {
#pragma unroll
            for (int i = 0; i < 8; i++) {
                float hi = tf32f(rb[i]);
                B0[(bnn_k + i * 2) * LDS_B + bnn_n] = hi;
                if (COMP) B1[(bnn_k + i * 2) * LDS_B + bnn_n] = tf32f(rb[i] - hi);
            }
        } else {
#pragma unroll
            for (int i = 0; i < 8; i++) {
                float hi = tf32f(rb[i]);
                B0[bnt_k * LDS_B + bnt_n + i * 16] = hi;
                if (COMP) B1[bnt_k * LDS_B + bnt_n + i * 16] = tf32f(rb[i] - hi);
            }
        }
    };

    auto compute = [&](int st) {
        const float* A0 = smem + st * STAGE;
        const float* A1 = A0 + APLANE;
        const float* B0 = A0 + NSP * APLANE;
        const float* B1 = B0 + BPLANE;
#pragma unroll
        for (int ks = 0; ks < 2; ks++) {
            const int k0 = ks * 8;
            unsigned bh[4][2], bl[4][2];
#pragma unroll
            for (int j = 0; j < 4; j++) {
                int n = bn_base + j * 8 + qr;
                bh[j][0] = __float_as_uint(B0[(k0 + qc) * LDS_B + n]);
                bh[j][1] = __float_as_uint(B0[(k0 + 4 + qc) * LDS_B + n]);
                if (COMP) {
                    bl[j][0] = __float_as_uint(B1[(k0 + qc) * LDS_B + n]);
                    bl[j][1] = __float_as_uint(B1[(k0 + 4 + qc) * LDS_B + n]);
                }
            }
#pragma unroll
            for (int i = 0; i < 4; i++) {
                int m = am_base + i * 16 + qr;
                unsigned ah[4], al[4];
                ah[0] = __float_as_uint(A0[(k0 + qc) * LDS_A + m]);
                ah[1] = __float_as_uint(A0[(k0 + qc) * LDS_A + m + 8]);
                ah[2] = __float_as_uint(A0[(k0 + 4 + qc) * LDS_A + m]);
                ah[3] = __float_as_uint(A0[(k0 + 4 + qc) * LDS_A + m + 8]);
                if (COMP) {
                    al[0] = __float_as_uint(A1[(k0 + qc) * LDS_A + m]);
                    al[1] = __float_as_uint(A1[(k0 + qc) * LDS_A + m + 8]);
                    al[2] = __float_as_uint(A1[(k0 + 4 + qc) * LDS_A + m]);
                    al[3] = __float_as_uint(A1[(k0 + 4 + qc) * LDS_A + m + 8]);
                }
#pragma unroll
                for (int j = 0; j < 4; j++) {
                    if (COMP) {
                        mma_tf32(acc[i][j], al, bh[j]);   // A_lo * B_hi
                        mma_tf32(acc[i][j], ah, bl[j]);   // A_hi * B_lo
                    }
                    mma_tf32(acc[i][j], ah, bh[j]);       // A_hi * B_hi
                }
            }
        }
    };

    // prologue: tile 0 into stage 0
    load_regs(0);
    store_smem(0);
    __syncthreads();

    for (int t = 0; t < ntiles; t++) {
        bool more = (t + 1 < ntiles);
        if (more) load_regs((t + 1) * BK);
        compute(t & 1);
        if (more) {
            store_smem((t + 1) & 1);       // disjoint buffer from the one being read
            __syncthreads();
        }
    }

    // epilogue: c0,c1 at (r, c),(r, c+1); c2,c3 at (r+8, ...)
#pragma unroll
    for (int i = 0; i < 4; i++) {
#pragma unroll
        for (int j = 0; j < 4; j++) {
            int r0 = bm + am_base + i * 16 + qr;
            int c0 = bn + bn_base + j * 8 + qc * 2;
#pragma unroll
            for (int half = 0; half < 2; half++) {
                int r = r0 + half * 8;
                if (r >= M) continue;
                float v0 = alpha * acc[i][j][half * 2 + 0];
                float v1 = alpha * acc[i][j][half * 2 + 1];
                if (c0 < N) {
                    if (RESID) v0 += R[(long)r * ldd + c0];
                    D[(long)r * ldd + c0] = v0;
                }
                if (c0 + 1 < N) {
                    if (RESID) v1 += R[(long)r * ldd + c0 + 1];
                    D[(long)r * ldd + c0 + 1] = v1;
                }
            }
        }
    }
}

static inline dim3 gemm_grid(int M, int N, int Z) {
    return dim3((N + 127) / 128, (M + 127) / 128, Z);
}

// smem bytes for the two variants (2 stages)
#define SH_COMP  (2 * 2 * (16 * 132 + 16 * 132) * 4)   // 67584
#define SH_PLAIN (2 * 1 * (16 * 132 + 16 * 132) * 4)   // 33792

// ---------------- host orchestration ----------------------------------------
// Math (exact reassociation of the reference; FFT == cosine transform):
//   F  = Re(FFT(qkv, axis=seq))
//   scores = (Fq (Wq Wk^T) Fk^T) / sqrt(160)
//   attn   = softmax(|scores|)
//   out    = x + (Re(FFT(attn @ Fv)) @ (Wv W_out)) / 2048
extern "C" void kernel_launch(void* const* d_in, const int* in_sizes, int n_in,
                              void* d_out, int out_size)
{
    const float* x     = (const float*)d_in[0];   // (4,2048,1280)
    const float* Wqkv  = (const float*)d_in[1];   // (1280, 975)
    const float* Wq    = (const float*)d_in[2];   // (325, 1280)
    const float* Wk    = (const float*)d_in[3];   // (325, 1280)
    const float* Wv    = (const float*)d_in[4];   // (325, 1280)
    const float* Wout  = (const float*)d_in[5];   // (1280, 1280)
    const float* gamma = (const float*)d_in[6];
    const float* beta  = (const float*)d_in[7];
    float* out = (float*)d_out;

    float *xn, *qkv, *F, *M, *T, *sc, *U, *Y, *Wvo;
    cudaGetSymbolAddress((void**)&xn,  g_xn);
    cudaGetSymbolAddress((void**)&qkv, g_qkv);
    cudaGetSymbolAddress((void**)&F,   g_F);
    cudaGetSymbolAddress((void**)&M,   g_M);
    cudaGetSymbolAddress((void**)&T,   g_T);
    cudaGetSymbolAddress((void**)&sc,  g_sc);
    cudaGetSymbolAddress((void**)&U,   g_U);
    cudaGetSymbolAddress((void**)&Y,   g_Y);
    cudaGetSymbolAddress((void**)&Wvo, g_Wvo);

    // allow >48KB dynamic smem for the COMP variants (idempotent, cheap)
    cudaFuncSetAttribute(tgemm_kernel<false, false, true>,
                         cudaFuncAttributeMaxDynamicSharedMemorySize, SH_COMP);
    cudaFuncSetAttribute(tgemm_kernel<true, false, true>,
                         cudaFuncAttributeMaxDynamicSharedMemorySize, SH_COMP);
    cudaFuncSetAttribute(tgemm_kernel<false, false, false>,
                         cudaFuncAttributeMaxDynamicSharedMemorySize, SH_PLAIN);
    cudaFuncSetAttribute(tgemm_kernel<false, true, false>,
                         cudaFuncAttributeMaxDynamicSharedMemorySize, SH_PLAIN);

    const long sF = (long)SEQ * R3;        // per-batch stride of qkv / F
    const long sR = (long)SEQ * RNK;       // per-batch stride of T / U / Y
    const long sS = (long)SEQ * SEQ;       // per-batch stride of scores
    const float inv_sqrt_hd = 0.07905694150420949f;  // 1/sqrt(160)

    // 1. LayerNorm
    layernorm_kernel<<<TOK, 256>>>(x, gamma, beta, xn);

    // 2. qkv = xn @ W_qkv                 (8192 x 975 x 1280)  [COMP]
    tgemm_kernel<false, false, true><<<gemm_grid(TOK, R3, 1), 256, SH_COMP>>>(
        TOK, R3, EMB, xn, EMB, 0L, Wqkv, R3, 0L, qkv, R3, 0L, 1.f, nullptr);

    // 3. F = Re(FFT(qkv)) along seq       (fp32 FFT; replaces C @ qkv)
    fft_real_kernel<<<dim3(R3, NBAT), 256>>>(qkv, F, R3, sF, 1.0f);

    // 4. M = Wq @ Wk^T                    (325 x 325 x 1280, NT)  [COMP]
    tgemm_kernel<true, false, true><<<gemm_grid(RNK, RNK, 1), 256, SH_COMP>>>(
        RNK, RNK, EMB, Wq, EMB, 0L, Wk, EMB, 0L, M, RNK, 0L, 1.f, nullptr);

    // 5. T = Fq @ M                       (z=4: 2048 x 325 x 325)  [COMP]
    tgemm_kernel<false, false, true><<<gemm_grid(SEQ, RNK, NBAT), 256, SH_COMP>>>(
        SEQ, RNK, RNK, F + 0 * RNK, R3, sF, M, RNK, 0L, T, RNK, sR, 1.f, nullptr);

    // 6. scores = (T @ Fk^T) / sqrt(160)  (z=4: 2048 x 2048 x 325, NT)  [COMP]
    tgemm_kernel<true, false, true><<<gemm_grid(SEQ, SEQ, NBAT), 256, SH_COMP>>>(
        SEQ, SEQ, RNK, T, RNK, sR, F + 1 * RNK, R3, sF, sc, SEQ, sS, inv_sqrt_hd, nullptr);

    // 7. attn = softmax(|scores|) rowwise, in place
    softmax_abs_kernel<<<NBAT * SEQ, 256>>>(sc);

    // 8. U = attn @ Fv                    (z=4: 2048 x 325 x 2048)  [tf32]
    tgemm_kernel<false, false, false><<<gemm_grid(SEQ, RNK, NBAT), 256, SH_PLAIN>>>(
        SEQ, RNK, SEQ, sc, SEQ, sS, F + 2 * RNK, R3, sF, U, RNK, sR, 1.f, nullptr);

    // 9. Y = Re(FFT(U))                   (fp32 FFT; replaces C @ U; 1/2048 folded below)
    fft_real_kernel<<<dim3(RNK, NBAT), 256>>>(U, Y, RNK, sR, 1.0f);

    // 10. Wvo = Wv @ W_out                (325 x 1280 x 1280)  [tf32]
    tgemm_kernel<false, false, false><<<gemm_grid(RNK, EMB, 1), 256, SH_PLAIN>>>(
        RNK, EMB, EMB, Wv, EMB, 0L, Wout, EMB, 0L, Wvo, EMB, 0L, 1.f, nullptr);

    // 11. out = x + (Y @ Wvo) / 2048      (8192 x 1280 x 325, residual)  [tf32]
    tgemm_kernel<false, true, false><<<gemm_grid(TOK, EMB, 1), 256, SH_PLAIN>>>(
        TOK, EMB, RNK, Y, RNK, 0L, Wvo, EMB, 0L, out, EMB, 0L, 1.0f / 2048.0f, x);
}

// round 8
// speedup vs baseline: 2.8487x; 1.4858x over previous
#include <cuda_runtime.h>
#include <math.h>
#include <stdint.h>

// ---------------- problem constants ----------------
#define SEQ   2048
#define EMB   1280
#define RNK   325          // low rank
#define R3    (3*RNK)      // 975
#define RNKP  328          // padded rank   (328*4B = 16B-multiple)
#define R3P   (3*RNKP)     // 984 padded qkv width
#define NBAT  4
#define TOK   (NBAT*SEQ)   // 8192 tokens
#define KS_M   10          // split-K slices for M   (1280/128)
#define KS_WVO 5           // split-K slices for Wvo (1280/256)

// ---------------- scratch (device globals; no allocations allowed) ----------
__device__ __align__(256) float g_xn   [(size_t)TOK*EMB];
__device__ __align__(256) float g_Wqp  [(size_t)EMB*R3P];        // padded W_qkv
__device__ __align__(256) float g_qkv  [(size_t)TOK*R3P];
__device__ __align__(256) float g_F    [(size_t)TOK*R3P];        // Re(FFT(qkv))
__device__ __align__(256) float g_Mp   [(size_t)KS_M*RNKP*RNKP]; // split-K partials
__device__ __align__(256) float g_M    [(size_t)RNKP*RNKP];      // Wq @ Wk^T
__device__ __align__(256) float g_T    [(size_t)TOK*RNKP];
__device__ __align__(256) float g_sc   [(size_t)NBAT*SEQ*SEQ];   // scores / attn
__device__ __align__(256) float g_U    [(size_t)TOK*RNKP];
__device__ __align__(256) float g_Y    [(size_t)TOK*RNKP];
__device__ __align__(256) float g_Wvop [(size_t)KS_WVO*RNKP*EMB];
__device__ __align__(256) float g_Wvo  [(size_t)RNKP*EMB];

// ---------------- helpers ----------------------------------------------------
__device__ __forceinline__ unsigned f2tf32(float x) {
    unsigned r;
    asm("cvt.rna.tf32.f32 %0, %1;" : "=r"(r) : "f"(x));
    return r;
}
__device__ __forceinline__ void mma_tf32(float (&c)[4],
                                         const unsigned (&a)[4],
                                         const unsigned (&b)[2]) {
    asm volatile(
        "mma.sync.aligned.m16n8k8.row.col.f32.tf32.tf32.f32 "
        "{%0,%1,%2,%3}, {%4,%5,%6,%7}, {%8,%9}, {%0,%1,%2,%3};"
        : "+f"(c[0]), "+f"(c[1]), "+f"(c[2]), "+f"(c[3])
        : "r"(a[0]), "r"(a[1]), "r"(a[2]), "r"(a[3]), "r"(b[0]), "r"(b[1]));
}
__device__ __forceinline__ void cp16(uint32_t s, const void* g, int bytes) {
    asm volatile("cp.async.cg.shared.global [%0], [%1], 16, %2;"
                 :: "r"(s), "l"(g), "r"(bytes));
}
__device__ __forceinline__ void cp_commit() { asm volatile("cp.async.commit_group;"); }
__device__ __forceinline__ void cp_wait1()  { asm volatile("cp.async.wait_group 1;"); }

// ---------------- pad W_qkv (1280 x 975) -> (1280 x 984), zero pads ----------
__global__ void pad_wqkv_kernel(const float* __restrict__ W, float* __restrict__ Wp)
{
    int idx = blockIdx.x * 256 + threadIdx.x;
    if (idx >= EMB * R3P) return;
    int row = idx / R3P, col = idx % R3P;
    int p = col / RNKP, r = col % RNKP;
    Wp[idx] = (r < RNK) ? W[row * R3 + p * RNK + r] : 0.f;
}

// ---------------- split-K reduce: dst[i] = alpha * sum_s parts[i+s*plane] ----
__global__ void reduce_parts_kernel(float* __restrict__ dst,
                                    const float* __restrict__ parts,
                                    long count, int nparts, long plane, float alpha)
{
    long i = (long)blockIdx.x * 256 + threadIdx.x;
    if (i >= count) return;
    float s = 0.f;
    for (int p = 0; p < nparts; p++) s += parts[i + (long)p * plane];
    dst[i] = alpha * s;
}

// ---------------- batched 2048-pt FFT along seq, keep real part --------------
// One block = one column; twiddle table in smem (computed once per block).
__global__ void __launch_bounds__(256)
fft_real_kernel(const float* __restrict__ in, float* __restrict__ out,
                int stride, long zstride, float scale)
{
    __shared__ float re[SEQ], im[SEQ];
    __shared__ float twr[1024], twi[1024];

    const int c = blockIdx.x;
    const int z = blockIdx.y;
    const float* src = in  + (long)z * zstride + c;
    float*       dst = out + (long)z * zstride + c;
    const int tid = threadIdx.x;

    // twiddle table: tw[j] = exp(-i*pi*j/1024)
#pragma unroll
    for (int i = 0; i < 4; i++) {
        int j = tid + i * 256;
        sincospif(-(float)j * (1.0f / 1024.0f), &twi[j], &twr[j]);
    }
    // load with bit-reversal (11-bit), imag = 0
#pragma unroll
    for (int i = 0; i < 8; i++) {
        int n = tid + i * 256;
        int r = __brev((unsigned)n) >> 21;
        re[r] = src[(long)n * stride];
        im[r] = 0.f;
    }
    __syncthreads();

#pragma unroll
    for (int s = 1; s <= 11; s++) {
        const int half = 1 << (s - 1);
        const int shf  = 11 - s;
#pragma unroll
        for (int i = 0; i < 4; i++) {
            int b   = tid + i * 256;
            int j   = b & (half - 1);
            int grp = b >> (s - 1);
            int i0  = (grp << s) + j;
            int i1  = i0 + half;
            float cs = twr[j << shf], sn = twi[j << shf];
            float xr = re[i1], xi = im[i1];
            float tr = xr * cs - xi * sn;
            float ti = xr * sn + xi * cs;
            float ur = re[i0], ui = im[i0];
            re[i0] = ur + tr;  im[i0] = ui + ti;
            re[i1] = ur - tr;  im[i1] = ui - ti;
        }
        __syncthreads();
    }
#pragma unroll
    for (int i = 0; i < 8; i++) {
        int n = tid + i * 256;
        dst[(long)n * stride] = scale * re[n];
    }
}

// ---------------- LayerNorm over E=1280 (one block per token) ----------------
__global__ void layernorm_kernel(const float* __restrict__ x,
                                 const float* __restrict__ gamma,
                                 const float* __restrict__ beta,
                                 float* __restrict__ y)
{
    int t   = blockIdx.x;
    int tid = threadIdx.x;
    const float* xr = x + (size_t)t * EMB;
    float*       yr = y + (size_t)t * EMB;

    float lv[5];
    float s = 0.f, s2 = 0.f;
#pragma unroll
    for (int i = 0; i < 5; i++) {
        float v = xr[tid + i * 256];
        lv[i] = v; s += v; s2 += v * v;
    }
#pragma unroll
    for (int o = 16; o > 0; o >>= 1) {
        s  += __shfl_xor_sync(0xffffffffu, s,  o);
        s2 += __shfl_xor_sync(0xffffffffu, s2, o);
    }
    __shared__ float sa[8], sb[8], smu, srs;
    int w = tid >> 5, l = tid & 31;
    if (l == 0) { sa[w] = s; sb[w] = s2; }
    __syncthreads();
    if (tid == 0) {
        float S = 0.f, S2 = 0.f;
#pragma unroll
        for (int i = 0; i < 8; i++) { S += sa[i]; S2 += sb[i]; }
        float mu  = S  * (1.0f / EMB);
        float var = S2 * (1.0f / EMB) - mu * mu;
        smu = mu; srs = rsqrtf(var + 1e-5f);
    }
    __syncthreads();
    float mu = smu, rs = srs;
#pragma unroll
    for (int i = 0; i < 5; i++) {
        int c = tid + i * 256;
        yr[c] = (lv[i] - mu) * rs * gamma[c] + beta[c];
    }
}

// ---------------- softmax(|row|) in place, row length 2048 -------------------
__global__ void softmax_abs_kernel(float* __restrict__ S)
{
    size_t r   = blockIdx.x;
    float* row = S + r * (size_t)SEQ;
    int tid = threadIdx.x;

    float v[8];
    float mx = -1e30f;
#pragma unroll
    for (int i = 0; i < 8; i++) {
        v[i] = fabsf(row[tid + i * 256]);
        mx = fmaxf(mx, v[i]);
    }
#pragma unroll
    for (int o = 16; o > 0; o >>= 1) mx = fmaxf(mx, __shfl_xor_sync(0xffffffffu, mx, o));
    __shared__ float sm[8], smax, ssum;
    int w = tid >> 5, l = tid & 31;
    if (l == 0) sm[w] = mx;
    __syncthreads();
    if (tid == 0) {
        float m = sm[0];
#pragma unroll
        for (int i = 1; i < 8; i++) m = fmaxf(m, sm[i]);
        smax = m;
    }
    __syncthreads();
    mx = smax;
    float s = 0.f;
#pragma unroll
    for (int i = 0; i < 8; i++) { v[i] = __expf(v[i] - mx); s += v[i]; }
#pragma unroll
    for (int o = 16; o > 0; o >>= 1) s += __shfl_xor_sync(0xffffffffu, s, o);
    if (l == 0) sm[w] = s;
    __syncthreads();
    if (tid == 0) {
        float t = 0.f;
#pragma unroll
        for (int i = 0; i < 8; i++) t += sm[i];
        ssum = t;
    }
    __syncthreads();
    float inv = 1.0f / ssum;
#pragma unroll
    for (int i = 0; i < 8; i++) row[tid + i * 256] = v[i] * inv;
}

// ---------------- tf32 tensor-core GEMM, cp.async 3-stage pipeline -----------
// D[z] = alpha * A[z](MxK) * op(B[z])(KxN)  (+ R[z] if RESID)
// Rows of A/B must be 16B-aligned (lda/ldb multiples of 4, aligned bases).
// smem holds raw fp32; tf32 conversion (hi, and lo when COMP) at fragment read.
// Per-z strides sA/sB/sD are ELEMENT offsets (also used for split-K slicing).
template <bool TRANSB, bool RESID, bool COMP>
__global__ void __launch_bounds__(256, 2)
tgemm_kernel(int M, int N, int K,
             const float* __restrict__ A, int lda, long sA,
             const float* __restrict__ B, int ldb, long sB,
             float* __restrict__ D, int ldd, long sD,
             float alpha, const float* __restrict__ R)
{
    constexpr int BM = 128, BN = 128, BK = 16;
    constexpr int A_ST  = 20;   // A smem: [m][k], 16+4 floats per row (conflict-free)
    constexpr int BNN_ST = 136; // B NN smem: [k][n], 128+8 (conflict-free frag reads)
    constexpr int BNT_ST = 20;  // B NT smem: [n][k]
    constexpr int A_FLOATS = BM * A_ST;                 // 2560
    constexpr int B_FLOATS = 2560;                      // covers 16*136=2176 and 128*20=2560
    constexpr int STAGE_FLOATS = A_FLOATS + B_FLOATS;   // 5120 (20480 B)
    extern __shared__ float smem[];

    const int z = blockIdx.z;
    A += (long)z * sA;
    B += (long)z * sB;
    D += (long)z * sD;
    if (RESID) R += (long)z * sD;

    const int bm = blockIdx.y * BM, bn = blockIdx.x * BN;
    const int tid = threadIdx.x;

    const int warp = tid >> 5, lane = tid & 31;
    const int wm = warp & 1, wn = warp >> 1;   // 2 x 4 warp grid; warp tile 64x32
    const int am_base = wm * 64;
    const int bn_base = wn * 32;
    const int qr = lane >> 2, qc = lane & 3;

    float acc[4][4][4];
#pragma unroll
    for (int i = 0; i < 4; i++)
#pragma unroll
        for (int j = 0; j < 4; j++)
#pragma unroll
            for (int e = 0; e < 4; e++) acc[i][j][e] = 0.f;

    const int ntiles = (K + BK - 1) / BK;

    auto issue_tile = [&](int kt, int st) {
        float* sa = smem + st * STAGE_FLOATS;
        float* sb = sa + A_FLOATS;
        uint32_t sau = (uint32_t)__cvta_generic_to_shared(sa);
        uint32_t sbu = (uint32_t)__cvta_generic_to_shared(sb);
        // A: 128 rows x 4 chunks of 16B
#pragma unroll
        for (int i = 0; i < 2; i++) {
            int cid = tid + i * 256;
            int m = cid >> 2, kc = cid & 3;
            int gm = bm + m, gk = kt + kc * 4;
            int bytes = 0;
            if (gm < M) {
                int rem = (K - gk) * 4;
                bytes = rem < 0 ? 0 : (rem > 16 ? 16 : rem);
            }
            const float* gp = (bytes > 0) ? (A + (long)gm * lda + gk) : A;
            cp16(sau + (m * A_ST + kc * 4) * 4, gp, bytes);
        }
        if (!TRANSB) {
            // B NN: 16 k-rows x 32 chunks
#pragma unroll
            for (int i = 0; i < 2; i++) {
                int cid = tid + i * 256;
                int k = cid >> 5, nc = cid & 31;
                int gk = kt + k, gn = bn + nc * 4;
                int bytes = 0;
                if (gk < K) {
                    int rem = (N - gn) * 4;
                    bytes = rem < 0 ? 0 : (rem > 16 ? 16 : rem);
                }
                const float* gp = (bytes > 0) ? (B + (long)gk * ldb + gn) : B;
                cp16(sbu + (k * BNN_ST + nc * 4) * 4, gp, bytes);
            }
        } else {
            // B NT: 128 n-rows x 4 chunks
#pragma unroll
            for (int i = 0; i < 2; i++) {
                int cid = tid + i * 256;
                int n = cid >> 2, kc = cid & 3;
                int gn = bn + n, gk = kt + kc * 4;
                int bytes = 0;
                if (gn < N) {
                    int rem = (K - gk) * 4;
                    bytes = rem < 0 ? 0 : (rem > 16 ? 16 : rem);
                }
                const float* gp = (bytes > 0) ? (B + (long)gn * ldb + gk) : B;
                cp16(sbu + (n * BNT_ST + kc * 4) * 4, gp, bytes);
            }
        }
    };

    auto compute = [&](int st) {
        const float* sa = smem + st * STAGE_FLOATS;
        const float* sb = sa + A_FLOATS;
#pragma unroll
        for (int ks = 0; ks < 2; ks++) {
            const int k0 = ks * 8;
            unsigned bh[4][2], bl[4][2];
#pragma unroll
            for (int j = 0; j < 4; j++) {
                int n = bn_base + j * 8 + qr;
                float r0, r1;
                if (!TRANSB) {
                    r0 = sb[(k0 + qc) * BNN_ST + n];
                    r1 = sb[(k0 + 4 + qc) * BNN_ST + n];
                } else {
                    r0 = sb[n * BNT_ST + k0 + qc];
                    r1 = sb[n * BNT_ST + k0 + 4 + qc];
                }
                bh[j][0] = f2tf32(r0);
                bh[j][1] = f2tf32(r1);
                if (COMP) {
                    bl[j][0] = f2tf32(r0 - __uint_as_float(bh[j][0]));
                    bl[j][1] = f2tf32(r1 - __uint_as_float(bh[j][1]));
                }
            }
#pragma unroll
            for (int i = 0; i < 4; i++) {
                int m = am_base + i * 16 + qr;
                float r0 = sa[m * A_ST + k0 + qc];
                float r1 = sa[(m + 8) * A_ST + k0 + qc];
                float r2 = sa[m * A_ST + k0 + 4 + qc];
                float r3 = sa[(m + 8) * A_ST + k0 + 4 + qc];
                unsigned ah[4], al[4];
                ah[0] = f2tf32(r0); ah[1] = f2tf32(r1);
                ah[2] = f2tf32(r2); ah[3] = f2tf32(r3);
                if (COMP) {
                    al[0] = f2tf32(r0 - __uint_as_float(ah[0]));
                    al[1] = f2tf32(r1 - __uint_as_float(ah[1]));
                    al[2] = f2tf32(r2 - __uint_as_float(ah[2]));
                    al[3] = f2tf32(r3 - __uint_as_float(ah[3]));
                }
#pragma unroll
                for (int j = 0; j < 4; j++) {
                    if (COMP) {
                        mma_tf32(acc[i][j], al, bh[j]);   // A_lo * B_hi
                        mma_tf32(acc[i][j], ah, bl[j]);   // A_hi * B_lo
                    }
                    mma_tf32(acc[i][j], ah, bh[j]);       // A_hi * B_hi
                }
            }
        }
    };

    // prologue: tiles 0,1 in flight
    issue_tile(0, 0);
    cp_commit();
    if (ntiles > 1) issue_tile(BK, 1);
    cp_commit();

    for (int t = 0; t < ntiles; t++) {
        cp_wait1();
        __syncthreads();
        int t2 = t + 2;
        if (t2 < ntiles) issue_tile(t2 * BK, t2 % 3);
        cp_commit();
        compute(t % 3);
    }

    // epilogue
#pragma unroll
    for (int i = 0; i < 4; i++) {
#pragma unroll
        for (int j = 0; j < 4; j++) {
            int r0 = bm + am_base + i * 16 + qr;
            int c0 = bn + bn_base + j * 8 + qc * 2;
#pragma unroll
            for (int half = 0; half < 2; half++) {
                int r = r0 + half * 8;
                if (r >= M) continue;
                float v0 = alpha * acc[i][j][half * 2 + 0];
                float v1 = alpha * acc[i][j][half * 2 + 1];
                if (c0 < N) {
                    if (RESID) v0 += R[(long)r * ldd + c0];
                    D[(long)r * ldd + c0] = v0;
                }
                if (c0 + 1 < N) {
                    if (RESID) v1 += R[(long)r * ldd + c0 + 1];
                    D[(long)r * ldd + c0 + 1] = v1;
                }
            }
        }
    }
}

static inline dim3 gemm_grid(int M, int N, int Z) {
    return dim3((N + 127) / 128, (M + 127) / 128, Z);
}

#define SH_GEMM (3 * 5120 * 4)   // 61440 B (3 stages)

// ---------------- host orchestration ----------------------------------------
// Math (exact reassociation of the reference; FFT == cosine transform):
//   F  = Re(FFT(qkv, axis=seq))
//   scores = (Fq (Wq Wk^T) Fk^T) / sqrt(160)
//   attn   = softmax(|scores|)
//   out    = x + (Re(FFT(attn @ Fv)) @ (Wv W_out)) / 2048
extern "C" void kernel_launch(void* const* d_in, const int* in_sizes, int n_in,
                              void* d_out, int out_size)
{
    const float* x     = (const float*)d_in[0];
    const float* Wqkv  = (const float*)d_in[1];
    const float* Wq    = (const float*)d_in[2];
    const float* Wk    = (const float*)d_in[3];
    const float* Wv    = (const float*)d_in[4];
    const float* Wout  = (const float*)d_in[5];
    const float* gamma = (const float*)d_in[6];
    const float* beta  = (const float*)d_in[7];
    float* out = (float*)d_out;

    float *xn, *Wqp, *qkv, *F, *Mp, *M, *T, *sc, *U, *Y, *Wvop, *Wvo;
    cudaGetSymbolAddress((void**)&xn,   g_xn);
    cudaGetSymbolAddress((void**)&Wqp,  g_Wqp);
    cudaGetSymbolAddress((void**)&qkv,  g_qkv);
    cudaGetSymbolAddress((void**)&F,    g_F);
    cudaGetSymbolAddress((void**)&Mp,   g_Mp);
    cudaGetSymbolAddress((void**)&M,    g_M);
    cudaGetSymbolAddress((void**)&T,    g_T);
    cudaGetSymbolAddress((void**)&sc,   g_sc);
    cudaGetSymbolAddress((void**)&U,    g_U);
    cudaGetSymbolAddress((void**)&Y,    g_Y);
    cudaGetSymbolAddress((void**)&Wvop, g_Wvop);
    cudaGetSymbolAddress((void**)&Wvo,  g_Wvo);

    cudaFuncSetAttribute(tgemm_kernel<false, false, true>,
                         cudaFuncAttributeMaxDynamicSharedMemorySize, SH_GEMM);
    cudaFuncSetAttribute(tgemm_kernel<true, false, true>,
                         cudaFuncAttributeMaxDynamicSharedMemorySize, SH_GEMM);
    cudaFuncSetAttribute(tgemm_kernel<false, false, false>,
                         cudaFuncAttributeMaxDynamicSharedMemorySize, SH_GEMM);
    cudaFuncSetAttribute(tgemm_kernel<false, true, false>,
                         cudaFuncAttributeMaxDynamicSharedMemorySize, SH_GEMM);

    const long sF  = (long)SEQ * R3P;       // per-batch stride of qkv / F
    const long sR  = (long)SEQ * RNKP;      // per-batch stride of T / U / Y
    const long sS  = (long)SEQ * SEQ;       // per-batch stride of scores
    const float inv_sqrt_hd = 0.07905694150420949f;  // 1/sqrt(160)

    // 0. pad W_qkv -> (1280 x 984), zero cols in each 328-block beyond 325
    pad_wqkv_kernel<<<(EMB * R3P + 255) / 256, 256>>>(Wqkv, Wqp);

    // 1. LayerNorm
    layernorm_kernel<<<TOK, 256>>>(x, gamma, beta, xn);

    // 2. qkv = xn @ Wqp              (8192 x 984 x 1280)  [COMP]
    tgemm_kernel<false, false, true><<<gemm_grid(TOK, R3P, 1), 256, SH_GEMM>>>(
        TOK, R3P, EMB, xn, EMB, 0L, Wqp, R3P, 0L, qkv, R3P, 0L, 1.f, nullptr);

    // 3. F = Re(FFT(qkv)) along seq  (pad columns are exact zeros -> FFT zeros)
    fft_real_kernel<<<dim3(R3P, NBAT), 256>>>(qkv, F, R3P, sF, 1.0f);

    // 4. M = Wq @ Wk^T  via split-K  (10 x [325 x 325 x 128], NT)  [COMP]
    tgemm_kernel<true, false, true><<<dim3(3, 3, KS_M), 256, SH_GEMM>>>(
        RNK, RNK, EMB / KS_M, Wq, EMB, (long)(EMB / KS_M),
        Wk, EMB, (long)(EMB / KS_M), Mp, RNKP, (long)RNKP * RNKP, 1.f, nullptr);
    reduce_parts_kernel<<<((long)RNK * RNKP + 255) / 256, 256>>>(
        M, Mp, (long)RNK * RNKP, KS_M, (long)RNKP * RNKP, 1.f);

    // 5. T = Fq @ M                  (z=4: 2048 x 325 x 325)  [COMP]
    tgemm_kernel<false, false, true><<<gemm_grid(SEQ, RNK, NBAT), 256, SH_GEMM>>>(
        SEQ, RNK, RNK, F, R3P, sF, M, RNKP, 0L, T, RNKP, sR, 1.f, nullptr);

    // 6. scores = (T @ Fk^T)/sqrt(160)  (z=4: 2048 x 2048 x 325, NT)  [COMP]
    tgemm_kernel<true, false, true><<<gemm_grid(SEQ, SEQ, NBAT), 256, SH_GEMM>>>(
        SEQ, SEQ, RNK, T, RNKP, sR, F + RNKP, R3P, sF, sc, SEQ, sS, inv_sqrt_hd, nullptr);

    // 7. attn = softmax(|scores|) rowwise, in place
    softmax_abs_kernel<<<NBAT * SEQ, 256>>>(sc);

    // 8. U = attn @ Fv               (z=4: 2048 x 325 x 2048)  [tf32]
    tgemm_kernel<false, false, false><<<gemm_grid(SEQ, RNK, NBAT), 256, SH_GEMM>>>(
        SEQ, RNK, SEQ, sc, SEQ, sS, F + 2 * RNKP, R3P, sF, U, RNKP, sR, 1.f, nullptr);

    // 9. Y = Re(FFT(U))              (valid 325 columns only)
    fft_real_kernel<<<dim3(RNK, NBAT), 256>>>(U, Y, RNKP, sR, 1.0f);

    // 10. Wvo = Wv @ Wout via split-K (5 x [325 x 1280 x 256])  [tf32]
    tgemm_kernel<false, false, false><<<dim3(10, 3, KS_WVO), 256, SH_GEMM>>>(
        RNK, EMB, EMB / KS_WVO, Wv, EMB, (long)(EMB / KS_WVO),
        Wout, EMB, (long)(EMB / KS_WVO) * EMB, Wvop, EMB, (long)RNKP * EMB, 1.f, nullptr);
    reduce_parts_kernel<<<((long)RNK * EMB + 255) / 256, 256>>>(
        Wvo, Wvop, (long)RNK * EMB, KS_WVO, (long)RNKP * EMB, 1.f);

    // 11. out = x + (Y @ Wvo)/2048   (8192 x 1280 x 325, residual)  [tf32]
    tgemm_kernel<false, true, false><<<gemm_grid(TOK, EMB, 1), 256, SH_GEMM>>>(
        TOK, EMB, RNK, Y, RNKP, 0L, Wvo, EMB, 0L, out, EMB, 0L, 1.0f / 2048.0f, x);
}